// round 4
// baseline (speedup 1.0000x reference)
#include <cuda_runtime.h>
#include <cuda_fp16.h>

// BlurNet: fake_B = w * mean_k bilinear(fake_S, pix + t_k*20*blurmap) + bias
//          offsets_flat[b, 2k+c] = t_k * 20 * blurmap[b, c],  t_k = (7-k)/7
// B=8, C=3, H=W=256. Output: fake_B (B*3*H*W) then offsets (B*30*H*W), f32.
//
// smem tile fp16, horizontal pair duplication:
//   Ap[r*80+c] = (c0,c1)@(r,c), (c0,c1)@(r,c+1)   8B  -> LDS.64
//   Cp[r*96+c] = (c2)@(r,c), (c2)@(r,c+1)          4B  -> LDS.32
// Strides 80/96 are 0 mod 16/32 entries => bank index is row-independent
// (pure ix), so small-offset samples are near conflict-free.

#define H 256
#define W 256
#define HW (H * W)
#define BATCH 8
#define TILE 32
#define HALO 20
#define TDIM (TILE + 2 * HALO)   // 72 rows / 72 used cols
#define APITCH 80                // 8B entries, 80 % 16 == 0
#define CPITCH 96                // 4B entries, 96 % 32 == 0
#define NTHREADS 256

__global__ __launch_bounds__(NTHREADS, 3)
void blurnet_kernel(const float* __restrict__ fake_S,
                    const float* __restrict__ blurmap,
                    const float* __restrict__ weight,
                    const float* __restrict__ bias,
                    float* __restrict__ out_fb,
                    float* __restrict__ out_off)
{
    extern __shared__ __align__(16) unsigned char smem_raw[];
    uint2*   Ap = (uint2*)smem_raw;                                  // 72*80*8  = 46080 B
    __half2* Cp = (__half2*)(smem_raw + TDIM * APITCH * 8);          // 72*96*4  = 27648 B

    const int tx0 = blockIdx.x * TILE;
    const int ty0 = blockIdx.y * TILE;
    const int b   = blockIdx.z;
    const int tid = threadIdx.x;

    const float* img  = fake_S  + (size_t)b * 3 * HW;
    const float* bm   = blurmap + (size_t)b * 2 * HW;
    float*       fb   = out_fb  + (size_t)b * 3 * HW;
    float*       offp = out_off + (size_t)b * 30 * HW;

    // ---- Phase 1: halo tile fill (issue loads early) ----
    #pragma unroll 5
    for (int p = tid; p < TDIM * TDIM; p += NTHREADS) {
        int r  = p / TDIM;
        int cc = p - r * TDIM;
        int gy = ty0 - HALO + r;
        int gx = tx0 - HALO + cc;
        float v0 = 0.f, v1 = 0.f, v2 = 0.f;   // (gy, gx)
        float u0 = 0.f, u1 = 0.f, u2 = 0.f;   // (gy, gx+1)
        bool rowok = (unsigned)gy < (unsigned)H;
        if (rowok && (unsigned)gx < (unsigned)W) {
            int gi = gy * W + gx;
            v0 = __ldg(img + gi);
            v1 = __ldg(img + gi + HW);
            v2 = __ldg(img + gi + 2 * HW);
        }
        if (rowok && (unsigned)(gx + 1) < (unsigned)W) {
            int gi = gy * W + gx + 1;
            u0 = __ldg(img + gi);
            u1 = __ldg(img + gi + HW);
            u2 = __ldg(img + gi + 2 * HW);
        }
        __half2 lo = __floats2half2_rn(v0, v1);
        __half2 hi = __floats2half2_rn(u0, u1);
        uint2 w;
        w.x = *(unsigned int*)&lo;
        w.y = *(unsigned int*)&hi;
        Ap[r * APITCH + cc] = w;
        Cp[r * CPITCH + cc] = __floats2half2_rn(v2, u2);
    }

    // ---- Phase 2: offsets output, vectorized (4 consecutive x per thread) ----
    {
        int ry = tid >> 3;            // 0..31
        int xq = (tid & 7) * 4;       // 0,4,...,28
        int gi = (ty0 + ry) * W + tx0 + xq;
        float4 b0 = *(const float4*)(bm + gi);
        float4 b1 = *(const float4*)(bm + gi + HW);
        float4 ob0 = make_float4(20.f * b0.x, 20.f * b0.y, 20.f * b0.z, 20.f * b0.w);
        float4 ob1 = make_float4(20.f * b1.x, 20.f * b1.y, 20.f * b1.z, 20.f * b1.w);
        #pragma unroll
        for (int k = 0; k < 15; k++) {
            const float t = (float)(7 - k) / 7.0f;
            float4 oy = make_float4(t * ob0.x, t * ob0.y, t * ob0.z, t * ob0.w);
            float4 ox = make_float4(t * ob1.x, t * ob1.y, t * ob1.z, t * ob1.w);
            *(float4*)(offp + (2 * k) * HW + gi)     = oy;
            *(float4*)(offp + (2 * k + 1) * HW + gi) = ox;
        }
    }
    __syncthreads();

    const float wgt = __ldg(weight) * (1.0f / 15.0f);
    const float bs  = __ldg(bias);

    // ---- Phase 3: blur, lane = x (clean bank pattern), 4 row iterations ----
    #pragma unroll 1
    for (int i = 0; i < (TILE * TILE) / NTHREADS; i++) {
        int p  = i * NTHREADS + tid;
        int yl = p >> 5;
        int xl = p & 31;
        int gy = ty0 + yl;
        int gx = tx0 + xl;
        int gidx = gy * W + gx;

        float ob0 = 20.0f * __ldg(bm + gidx);        // dy scale (ch0)
        float ob1 = 20.0f * __ldg(bm + gidx + HW);   // dx scale (ch1)

        // k = 7 (t = 0): exact center sample
        int ca = (yl + HALO) * APITCH + (xl + HALO);
        int cc = (yl + HALO) * CPITCH + (xl + HALO);
        uint2 cw = Ap[ca];
        float2 cl = __half22float2(*(__half2*)&cw.x);
        float2 cz = __half22float2(Cp[cc]);
        float s0 = cl.x, s1 = cl.y, s2 = cz.x;

        #pragma unroll
        for (int k = 0; k < 15; k++) {
            if (k == 7) continue;
            const float t = (float)(7 - k) / 7.0f;   // compile-time constant
            float oy = t * ob0;
            float ox = t * ob1;

            float fy  = (float)gy + oy;              // global coords = ref rounding
            float fx  = (float)gx + ox;
            float fy0 = floorf(fy);
            float fx0 = floorf(fx);
            float tyf = fy - fy0;
            float txf = fx - fx0;
            int iy = (int)fy0 - ty0 + HALO;
            int ix = (int)fx0 - tx0 + HALO;
            int baseA = iy * APITCH + ix;
            int baseC = iy * CPITCH + ix;

            uint2   w0 = Ap[baseA];              // row y0: (c0,c1)@x0,x1
            uint2   w1 = Ap[baseA + APITCH];     // row y1
            __half2 z0 = Cp[baseC];              // c2@(x0,x1), row y0
            __half2 z1 = Cp[baseC + CPITCH];     // row y1

            float2 p00 = __half22float2(*(__half2*)&w0.x);
            float2 p01 = __half22float2(*(__half2*)&w0.y);
            float2 p10 = __half22float2(*(__half2*)&w1.x);
            float2 p11 = __half22float2(*(__half2*)&w1.y);
            float2 q0  = __half22float2(z0);
            float2 q1  = __half22float2(z1);

            float w11f = tyf * txf;
            float w10f = tyf - w11f;
            float w01f = txf - w11f;
            float w00f = 1.0f - tyf - txf + w11f;

            s0 = fmaf(w00f, p00.x, s0); s0 = fmaf(w01f, p01.x, s0);
            s0 = fmaf(w10f, p10.x, s0); s0 = fmaf(w11f, p11.x, s0);
            s1 = fmaf(w00f, p00.y, s1); s1 = fmaf(w01f, p01.y, s1);
            s1 = fmaf(w10f, p10.y, s1); s1 = fmaf(w11f, p11.y, s1);
            s2 = fmaf(w00f, q0.x, s2);  s2 = fmaf(w01f, q0.y, s2);
            s2 = fmaf(w10f, q1.x, s2);  s2 = fmaf(w11f, q1.y, s2);
        }

        fb[gidx]          = fmaf(wgt, s0, bs);
        fb[gidx + HW]     = fmaf(wgt, s1, bs);
        fb[gidx + 2 * HW] = fmaf(wgt, s2, bs);
    }
}

extern "C" void kernel_launch(void* const* d_in, const int* in_sizes, int n_in,
                              void* d_out, int out_size)
{
    const float* fake_S  = (const float*)d_in[0];
    const float* blurmap = (const float*)d_in[1];
    const float* weight  = (const float*)d_in[2];
    const float* bias    = (const float*)d_in[3];

    float* out_fb  = (float*)d_out;
    float* out_off = (float*)d_out + (size_t)BATCH * 3 * HW;

    const int smem = TDIM * APITCH * 8 + TDIM * CPITCH * 4;   // 73,728 B
    static bool configured = false;
    if (!configured) {
        cudaFuncSetAttribute(blurnet_kernel,
                             cudaFuncAttributeMaxDynamicSharedMemorySize, smem);
        configured = true;
    }

    dim3 grid(W / TILE, H / TILE, BATCH);   // (8, 8, 8)
    blurnet_kernel<<<grid, NTHREADS, smem>>>(fake_S, blurmap, weight, bias,
                                             out_fb, out_off);
}